// round 13
// baseline (speedup 1.0000x reference)
#include <cuda_runtime.h>
#include <cuda_fp16.h>
#include <cstdint>

// ============================================================================
// TernaryConv2d: x[16,64,224,224] (*) TWN(weight[64,64,3,3]) + bias -> out fp32
//
// tw = alpha[co] * t, t in {-1,0,+1}  =>  out = alpha * conv(x, t) + bias
// Implicit GEMM per 128-pixel tile:
//   D[128 m, 64 n] = A[128, 576] * B[64, 576]^T
// A = fp16(x patches) (only rounding source), B = fp16 ternary (exact),
// fp32 accumulate via mma.sync.m16n8k16 (sm_103-legal; tcgen05 is rejected
// by this toolchain's PTX target).
// ============================================================================

#define CIN       64
#define HW        224
#define NHW       50176          // 224*224
#define NCHW1     3211264        // 64*50176
#define S_TOTAL   802816         // 16*224*224
#define N_TILES   6272           // S_TOTAL / 128
#define K_TOTAL   576
#define N_CHUNKS  9              // K chunks of 64

// SMEM layout (all 1024-aligned)
#define OFF_B      0             // 576 rows * 128B (fp16 [k][co], SW128)
#define OFF_A0     73728         // 128 rows * 128B
#define OFF_A1     90112
#define SMEM_BYTES 106496

#define SW128(o) ((o) ^ (((o) >> 3) & 0x70))

// Scratch (allocation-free rule: __device__ globals)
__device__ __align__(16) unsigned char g_Bsw[K_TOTAL * 128];
__device__ float g_alpha[64];

// ============================================================================
// helpers
// ============================================================================
__device__ __forceinline__ uint32_t smem_to_u32(const void* p) {
    uint32_t a;
    asm("{ .reg .u64 t; cvta.to.shared.u64 t, %1; cvt.u32.u64 %0, t; }"
        : "=r"(a) : "l"(p));
    return a;
}

__device__ __forceinline__ void ldsm_x4(uint32_t* r, uint32_t addr) {
    asm volatile("ldmatrix.sync.aligned.m8n8.x4.shared.b16 {%0,%1,%2,%3}, [%4];"
        : "=r"(r[0]), "=r"(r[1]), "=r"(r[2]), "=r"(r[3]) : "r"(addr));
}
__device__ __forceinline__ void ldsm_x4_t(uint32_t* r, uint32_t addr) {
    asm volatile("ldmatrix.sync.aligned.m8n8.x4.trans.shared.b16 {%0,%1,%2,%3}, [%4];"
        : "=r"(r[0]), "=r"(r[1]), "=r"(r[2]), "=r"(r[3]) : "r"(addr));
}
__device__ __forceinline__ void mma16816(float* c, const uint32_t* a, const uint32_t* b) {
    asm volatile(
        "mma.sync.aligned.m16n8k16.row.col.f32.f16.f16.f32 "
        "{%0,%1,%2,%3}, {%4,%5,%6,%7}, {%8,%9}, {%0,%1,%2,%3};"
        : "+f"(c[0]), "+f"(c[1]), "+f"(c[2]), "+f"(c[3])
        : "r"(a[0]), "r"(a[1]), "r"(a[2]), "r"(a[3]), "r"(b[0]), "r"(b[1]));
}
__device__ __forceinline__ uint32_t pack_h2(float lo, float hi) {
    __half2 h = __floats2half2_rn(lo, hi);
    return *reinterpret_cast<uint32_t*>(&h);
}
#define STS128(r0, r1, r2, r3, smem_addr) \
    asm volatile("st.shared.v4.b32 [%0], {%1, %2, %3, %4};" \
        :: "r"(smem_addr), "r"(r0), "r"(r1), "r"(r2), "r"(r3) : "memory")

// ============================================================================
// Prep: per-output-channel TWN ternarize.
// g_alpha[co]; g_Bsw = fp16 ternary stored [k=576][co=64], SW128 swizzled:
//   byte = SW128(k*128 + co*2)
// ============================================================================
__global__ void prep_ternarize(const float* __restrict__ w) {
    const int co = blockIdx.x;
    const float* wc = w + co * K_TOTAL;
    const int tid = threadIdx.x, lane = tid & 31, warp = tid >> 5;

    __shared__ float r1[8], r2[8], r3[8];
    __shared__ float sh_delta;

    float s = 0.f;
    for (int k = tid; k < K_TOTAL; k += 256) s += fabsf(wc[k]);
    #pragma unroll
    for (int o = 16; o; o >>= 1) s += __shfl_xor_sync(0xffffffffu, s, o);
    if (lane == 0) r1[warp] = s;
    __syncthreads();
    if (tid == 0) {
        float tot = 0.f;
        #pragma unroll
        for (int i = 0; i < 8; i++) tot += r1[i];
        sh_delta = (0.7f / 576.f) * tot;
    }
    __syncthreads();
    const float delta = sh_delta;

    float ms = 0.f, mc = 0.f;
    for (int k = tid; k < K_TOTAL; k += 256) {
        float a = fabsf(wc[k]);
        if (a > delta) { ms += a; mc += 1.f; }
    }
    #pragma unroll
    for (int o = 16; o; o >>= 1) {
        ms += __shfl_xor_sync(0xffffffffu, ms, o);
        mc += __shfl_xor_sync(0xffffffffu, mc, o);
    }
    if (lane == 0) { r2[warp] = ms; r3[warp] = mc; }
    __syncthreads();
    if (tid == 0) {
        float tms = 0.f, tmc = 0.f;
        #pragma unroll
        for (int i = 0; i < 8; i++) { tms += r2[i]; tmc += r3[i]; }
        if (tmc < 0.5f) tmc = 1.f;
        float al = tms / tmc;
        if (al < 1e-4f) al = 1e-4f;
        g_alpha[co] = al;
    }

    for (int k = tid; k < K_TOTAL; k += 256) {
        float wv = wc[k];
        float tv = (wv > delta) ? 1.f : ((wv < -delta) ? -1.f : 0.f);
        unsigned off = SW128((unsigned)k * 128u + (unsigned)co * 2u);
        *reinterpret_cast<__half*>(g_Bsw + off) = __float2half_rn(tv);
    }
}

// ============================================================================
// Persistent implicit-GEMM conv. 256 threads = 8 warps: 4 along M(32) x 2
// along N(32). Per tile (128 pixels): 9 K-chunks of 64, A double-buffered,
// next chunk's gmem loads prefetched into registers during current MMAs.
// ============================================================================
__global__ void __launch_bounds__(256)
ternary_conv_kernel(const float* __restrict__ x,
                    const float* __restrict__ bias,
                    float* __restrict__ out) {
    extern __shared__ __align__(1024) unsigned char smem[];
    const uint32_t sb = smem_to_u32(smem);
    const int tid  = threadIdx.x;
    const int wid  = tid >> 5;
    const int lane = tid & 31;
    const int wm   = wid & 3;          // M warp (32 rows)
    const int wn   = wid >> 2;         // N warp (32 cols)
    const int mbase = wm * 32;
    const int nbase = wn * 32;
    const int lm = lane & 15, lh = lane >> 4;

    // ---- one-time: copy pre-swizzled B image into SMEM ----
    {
        const uint4* src = reinterpret_cast<const uint4*>(g_Bsw);
        uint4* dst = reinterpret_cast<uint4*>(smem + OFF_B);
        for (int i = tid; i < (K_TOTAL * 128) / 16; i += 256) dst[i] = src[i];
    }
    // per-thread alpha/bias for the 8 co this thread owns in the epilogue
    const int cc2 = (lane & 3) * 2;
    float al[8], bi[8];
    #pragma unroll
    for (int ni = 0; ni < 4; ni++) {
        #pragma unroll
        for (int b = 0; b < 2; b++) {
            int co = nbase + ni * 8 + cc2 + b;
            al[ni * 2 + b] = g_alpha[co];
            bi[ni * 2 + b] = bias[co];
        }
    }
    __syncthreads();

    for (int t = blockIdx.x; t < N_TILES; t += gridDim.x) {
        // ---- per-tile spatial bases (4 pixel groups of 32) ----
        int base_[4], hm1_[4], wm1_[4];
        #pragma unroll
        for (int pb = 0; pb < 4; pb++) {
            const unsigned s = (unsigned)t * 128u + (unsigned)(pb * 32 + lane);
            const unsigned n = s / (unsigned)NHW;
            const unsigned r2 = s - n * (unsigned)NHW;
            const unsigned h = r2 / (unsigned)HW;
            const unsigned w = r2 - h * (unsigned)HW;
            base_[pb] = (int)(n * (unsigned)NCHW1 + h * (unsigned)HW + w) - 225;
            hm1_[pb] = (int)h - 1;
            wm1_[pb] = (int)w - 1;
        }

        float acc[32];
        #pragma unroll
        for (int i = 0; i < 32; i++) acc[i] = 0.f;

        float xv[4][8];
        // k-octet decomposition for a chunk: this warp covers k in
        // [c*64 + wid*8, +8)
        int cterm[8], kho[8], kwo[8];

        // ---- load chunk 0 ----
        {
            const int kgb = 0 * 64 + wid * 8;
            #pragma unroll
            for (int j = 0; j < 8; j++) {
                int kg = kgb + j;
                int ci = (unsigned)kg / 9u;
                int r = kg - ci * 9;
                int kh = (r >= 6) ? 2 : (r >= 3 ? 1 : 0);
                int kw = r - kh * 3;
                kho[j] = kh; kwo[j] = kw;
                cterm[j] = ci * NHW + kh * HW + kw;
            }
            #pragma unroll
            for (int pb = 0; pb < 4; pb++) {
                #pragma unroll
                for (int j = 0; j < 8; j++) {
                    bool v = ((unsigned)(hm1_[pb] + kho[j]) < (unsigned)HW) &&
                             ((unsigned)(wm1_[pb] + kwo[j]) < (unsigned)HW);
                    xv[pb][j] = v ? __ldg(x + base_[pb] + cterm[j]) : 0.f;
                }
            }
        }
        // ---- store chunk 0 ----
        #pragma unroll
        for (int pb = 0; pb < 4; pb++) {
            uint32_t u0 = pack_h2(xv[pb][0], xv[pb][1]);
            uint32_t u1 = pack_h2(xv[pb][2], xv[pb][3]);
            uint32_t u2 = pack_h2(xv[pb][4], xv[pb][5]);
            uint32_t u3 = pack_h2(xv[pb][6], xv[pb][7]);
            uint32_t off = SW128((uint32_t)(pb * 32 + lane) * 128u + (uint32_t)wid * 16u);
            STS128(u0, u1, u2, u3, sb + OFF_A0 + off);
        }
        __syncthreads();

        // ---- K-chunk loop ----
        #pragma unroll 1
        for (int c = 0; c < N_CHUNKS; ++c) {
            // prefetch chunk c+1 into registers (overlaps with MMAs below)
            if (c + 1 < N_CHUNKS) {
                const int kgb = (c + 1) * 64 + wid * 8;
                #pragma unroll
                for (int j = 0; j < 8; j++) {
                    int kg = kgb + j;
                    int ci = (unsigned)kg / 9u;
                    int r = kg - ci * 9;
                    int kh = (r >= 6) ? 2 : (r >= 3 ? 1 : 0);
                    int kw = r - kh * 3;
                    kho[j] = kh; kwo[j] = kw;
                    cterm[j] = ci * NHW + kh * HW + kw;
                }
                #pragma unroll
                for (int pb = 0; pb < 4; pb++) {
                    #pragma unroll
                    for (int j = 0; j < 8; j++) {
                        bool v = ((unsigned)(hm1_[pb] + kho[j]) < (unsigned)HW) &&
                                 ((unsigned)(wm1_[pb] + kwo[j]) < (unsigned)HW);
                        xv[pb][j] = v ? __ldg(x + base_[pb] + cterm[j]) : 0.f;
                    }
                }
            }

            // MMAs on chunk c from SMEM buffer c&1
            const uint32_t abuf = sb + ((c & 1) ? OFF_A1 : OFF_A0);
            #pragma unroll
            for (int ks = 0; ks < 4; ks++) {
                uint32_t a0[4], a1[4], b0[4], b1[4];
                ldsm_x4(a0, abuf + SW128((uint32_t)(mbase + lm) * 128u
                                         + (uint32_t)(ks * 32 + lh * 16)));
                ldsm_x4(a1, abuf + SW128((uint32_t)(mbase + 16 + lm) * 128u
                                         + (uint32_t)(ks * 32 + lh * 16)));
                const uint32_t kRow = (uint32_t)(c * 64 + ks * 16 + lm);
                ldsm_x4_t(b0, sb + OFF_B + SW128(kRow * 128u
                                         + (uint32_t)(nbase + lh * 8) * 2u));
                ldsm_x4_t(b1, sb + OFF_B + SW128(kRow * 128u
                                         + (uint32_t)(nbase + 16 + lh * 8) * 2u));
                mma16816(acc + 0,  a0, b0 + 0);
                mma16816(acc + 4,  a0, b0 + 2);
                mma16816(acc + 8,  a0, b1 + 0);
                mma16816(acc + 12, a0, b1 + 2);
                mma16816(acc + 16, a1, b0 + 0);
                mma16816(acc + 20, a1, b0 + 2);
                mma16816(acc + 24, a1, b1 + 0);
                mma16816(acc + 28, a1, b1 + 2);
            }

            // store prefetched chunk c+1, then barrier
            if (c + 1 < N_CHUNKS) {
                const uint32_t nbuf = sb + (((c + 1) & 1) ? OFF_A1 : OFF_A0);
                #pragma unroll
                for (int pb = 0; pb < 4; pb++) {
                    uint32_t u0 = pack_h2(xv[pb][0], xv[pb][1]);
                    uint32_t u1 = pack_h2(xv[pb][2], xv[pb][3]);
                    uint32_t u2 = pack_h2(xv[pb][4], xv[pb][5]);
                    uint32_t u3 = pack_h2(xv[pb][6], xv[pb][7]);
                    uint32_t off = SW128((uint32_t)(pb * 32 + lane) * 128u
                                         + (uint32_t)wid * 16u);
                    STS128(u0, u1, u2, u3, nbuf + off);
                }
                __syncthreads();
            }
        }
        __syncthreads();   // protect A buffers before next tile's build

        // ---- epilogue: acc * alpha + bias -> gmem ----
        const int pr = lane >> 2;
        #pragma unroll
        for (int mi = 0; mi < 2; mi++) {
            #pragma unroll
            for (int rh = 0; rh < 2; rh++) {
                const unsigned s = (unsigned)(t * 128 + mbase + mi * 16 + rh * 8 + pr);
                const unsigned n = s / (unsigned)NHW;
                const unsigned r2 = s - n * (unsigned)NHW;
                const unsigned h = r2 / (unsigned)HW;
                const unsigned w = r2 - h * (unsigned)HW;
                float* op = out + (size_t)(n * (unsigned)NCHW1
                                           + h * (unsigned)HW + w);
                #pragma unroll
                for (int ni = 0; ni < 4; ni++) {
                    #pragma unroll
                    for (int b = 0; b < 2; b++) {
                        const int co = nbase + ni * 8 + cc2 + b;
                        const float v = acc[(mi * 4 + ni) * 4 + rh * 2 + b];
                        op[(size_t)co * NHW] = v * al[ni * 2 + b] + bi[ni * 2 + b];
                    }
                }
            }
        }
    }
}

// ============================================================================
// kernel_launch
// ============================================================================
extern "C" void kernel_launch(void* const* d_in, const int* in_sizes, int n_in,
                              void* d_out, int out_size) {
    const float* x    = (const float*)d_in[0];
    const float* wgt  = (const float*)d_in[1];
    const float* bias = (const float*)d_in[2];
    float* out = (float*)d_out;

    cudaFuncSetAttribute(ternary_conv_kernel,
                         cudaFuncAttributeMaxDynamicSharedMemorySize, SMEM_BYTES);

    prep_ternarize<<<64, 256>>>(wgt);
    ternary_conv_kernel<<<296, 256, SMEM_BYTES>>>(x, bias, out);
}

// round 14
// speedup vs baseline: 4.5150x; 4.5150x over previous
#include <cuda_runtime.h>
#include <cuda_fp16.h>
#include <cstdint>

// ============================================================================
// TernaryConv2d as shift-GEMM:
//   out[co] = alpha[co] * sum_{kh,kw} ( x_shift(kh,kw)[pix, ci] @ B(kh,kw)[co, ci]^T ) + bias
// Per CTA-tile = one output row (n,h): M=224 pixels, N=64, nine K=64 GEMMs.
// x rows staged once as padded fp16 [w_pad][ci] slabs (ring of 4, +1 slab/row).
// mma.sync.m16n8k16 f16 -> f32. B ternary {-1,0,1} exact in fp16.
// ============================================================================

#define HW        224
#define NHW       50176
#define NCHW1     3211264
#define ROWS_TOTAL 3584          // 16*224
#define K_TOTAL   576

#define SLAB_STRIDE 29696        // 29KB-aligned, >= 226*128
#define SLAB_BYTES  28928        // 226 rows * 128B
#define OFF_B       0            // 9 * 8192 = 73728
#define OFF_SLAB    73728
#define SMEM_BYTES  (OFF_SLAB + 4 * SLAB_STRIDE)   // 192512

#define SW128(o) ((o) ^ (((o) >> 3) & 0x70))

// Scratch (allocation-free rule: __device__ globals)
__device__ __align__(16) unsigned char g_Bsw[9 * 8192];
__device__ float g_alpha[64];

// ============================================================================
// helpers
// ============================================================================
__device__ __forceinline__ uint32_t smem_to_u32(const void* p) {
    uint32_t a;
    asm("{ .reg .u64 t; cvta.to.shared.u64 t, %1; cvt.u32.u64 %0, t; }"
        : "=r"(a) : "l"(p));
    return a;
}
__device__ __forceinline__ void ldsm_x4(uint32_t* r, uint32_t addr) {
    asm volatile("ldmatrix.sync.aligned.m8n8.x4.shared.b16 {%0,%1,%2,%3}, [%4];"
        : "=r"(r[0]), "=r"(r[1]), "=r"(r[2]), "=r"(r[3]) : "r"(addr));
}
__device__ __forceinline__ void ldsm_x4_t(uint32_t* r, uint32_t addr) {
    asm volatile("ldmatrix.sync.aligned.m8n8.x4.trans.shared.b16 {%0,%1,%2,%3}, [%4];"
        : "=r"(r[0]), "=r"(r[1]), "=r"(r[2]), "=r"(r[3]) : "r"(addr));
}
__device__ __forceinline__ void mma16816(float* c, const uint32_t* a, const uint32_t* b) {
    asm volatile(
        "mma.sync.aligned.m16n8k16.row.col.f32.f16.f16.f32 "
        "{%0,%1,%2,%3}, {%4,%5,%6,%7}, {%8,%9}, {%0,%1,%2,%3};"
        : "+f"(c[0]), "+f"(c[1]), "+f"(c[2]), "+f"(c[3])
        : "r"(a[0]), "r"(a[1]), "r"(a[2]), "r"(a[3]), "r"(b[0]), "r"(b[1]));
}
__device__ __forceinline__ uint32_t pack_h2(float lo, float hi) {
    __half2 h = __floats2half2_rn(lo, hi);
    return *reinterpret_cast<uint32_t*>(&h);
}

// ============================================================================
// Prep: TWN ternarize. g_alpha[co]; g_Bsw holds, per gemm g=kh*3+kw, a
// [ci=64 rows][128B of co halves] SW128 tile at offset g*8192.
// ============================================================================
__global__ void prep_ternarize(const float* __restrict__ w) {
    const int co = blockIdx.x;
    const float* wc = w + co * K_TOTAL;
    const int tid = threadIdx.x, lane = tid & 31, warp = tid >> 5;

    __shared__ float r1[8], r2[8], r3[8];
    __shared__ float sh_delta;

    float s = 0.f;
    for (int k = tid; k < K_TOTAL; k += 256) s += fabsf(wc[k]);
    #pragma unroll
    for (int o = 16; o; o >>= 1) s += __shfl_xor_sync(0xffffffffu, s, o);
    if (lane == 0) r1[warp] = s;
    __syncthreads();
    if (tid == 0) {
        float tot = 0.f;
        #pragma unroll
        for (int i = 0; i < 8; i++) tot += r1[i];
        sh_delta = (0.7f / 576.f) * tot;
    }
    __syncthreads();
    const float delta = sh_delta;

    float ms = 0.f, mc = 0.f;
    for (int k = tid; k < K_TOTAL; k += 256) {
        float a = fabsf(wc[k]);
        if (a > delta) { ms += a; mc += 1.f; }
    }
    #pragma unroll
    for (int o = 16; o; o >>= 1) {
        ms += __shfl_xor_sync(0xffffffffu, ms, o);
        mc += __shfl_xor_sync(0xffffffffu, mc, o);
    }
    if (lane == 0) { r2[warp] = ms; r3[warp] = mc; }
    __syncthreads();
    if (tid == 0) {
        float tms = 0.f, tmc = 0.f;
        #pragma unroll
        for (int i = 0; i < 8; i++) { tms += r2[i]; tmc += r3[i]; }
        if (tmc < 0.5f) tmc = 1.f;
        float al = tms / tmc;
        if (al < 1e-4f) al = 1e-4f;
        g_alpha[co] = al;
    }

    for (int k = tid; k < K_TOTAL; k += 256) {
        float wv = wc[k];
        float tv = (wv > delta) ? 1.f : ((wv < -delta) ? -1.f : 0.f);
        unsigned ci = (unsigned)k / 9u;
        unsigned g  = (unsigned)k - ci * 9u;    // kh*3+kw
        unsigned off = g * 8192u + SW128(ci * 128u + (unsigned)co * 2u);
        *reinterpret_cast<__half*>(g_Bsw + off) = __float2half_rn(tv);
    }
}

// ============================================================================
// Slab loader: padded image row p (unpadded u=p-1) of image n -> ring slot p&3.
// Layout: [wp=0..225] rows of 128B (64 ci halves), SW128 swizzled. Pads zero.
// Warp w covers ci [w*8, w*8+8); lanes stride the 224 w positions (coalesced).
// ============================================================================
__device__ __forceinline__ void load_slab(uint32_t sb, const float* __restrict__ x,
                                          int n, int p, int tid) {
    const uint32_t slot = sb + OFF_SLAB + (uint32_t)(p & 3) * SLAB_STRIDE;
    const int u = p - 1;
    if ((unsigned)u < (unsigned)HW) {
        const int lane = tid & 31;
        const int cib = (tid >> 5) * 8;
        const float* bp = x + (size_t)(n * 64 + cib) * NHW + (size_t)u * HW;
        #pragma unroll
        for (int cp = 0; cp < 4; cp++) {
            const float* p0 = bp + (size_t)(cp * 2) * NHW;
            const float* p1 = p0 + NHW;
            #pragma unroll
            for (int wb = 0; wb < 7; wb++) {
                const int w = wb * 32 + lane;
                const uint32_t h2 = pack_h2(__ldg(p0 + w), __ldg(p1 + w));
                const uint32_t off =
                    SW128(((uint32_t)(w + 1) << 7) + (uint32_t)(cib + cp * 2) * 2u);
                asm volatile("st.shared.b32 [%0], %1;"
                    :: "r"(slot + off), "r"(h2) : "memory");
            }
        }
        if (lane < 4) {   // zero the wp=0 / wp=225 pad columns for this warp's ci
            const uint32_t c2 = (uint32_t)(cib + lane * 2) * 2u;
            asm volatile("st.shared.b32 [%0], %1;"
                :: "r"(slot + SW128(c2)), "r"(0u) : "memory");
            asm volatile("st.shared.b32 [%0], %1;"
                :: "r"(slot + SW128((225u << 7) + c2)), "r"(0u) : "memory");
        }
    } else {
        for (int i = tid; i < SLAB_BYTES / 16; i += 256) {
            asm volatile("st.shared.v4.b32 [%0], {%1,%2,%3,%4};"
                :: "r"(slot + (uint32_t)i * 16), "r"(0u), "r"(0u), "r"(0u), "r"(0u)
                : "memory");
        }
    }
}

// ============================================================================
// Main kernel: persistent CTAs walk contiguous (n,h) row ranges.
// 8 warps = 2M(112 rows) x 4N(16 co). Per row: 9 gemms x 4 k16 steps.
// ============================================================================
__global__ void __launch_bounds__(256, 1)
ternary_conv_kernel(const float* __restrict__ x,
                    const float* __restrict__ bias,
                    float* __restrict__ out) {
    extern __shared__ __align__(1024) unsigned char smem[];
    const uint32_t sb = smem_to_u32(smem);
    const int tid  = threadIdx.x;
    const int lane = tid & 31;
    const int wid  = tid >> 5;
    const int lm = lane & 15, lh = lane >> 4;
    const int wn = wid & 3, wm = wid >> 2;
    const int mbase = wm * 112;
    const int nbase = wn * 16;

    // one-time: copy pre-swizzled B into SMEM (73728B = 18*256 uint4)
    {
        const uint4* src = reinterpret_cast<const uint4*>(g_Bsw);
        uint4* dst = reinterpret_cast<uint4*>(smem + OFF_B);
        #pragma unroll
        for (int i = 0; i < 18; i++) dst[tid + i * 256] = src[tid + i * 256];
    }

    // per-thread epilogue constants (4 co values)
    const int q2 = (lane & 3) * 2;
    float al[4], bi[4];
    size_t coff[4];
    #pragma unroll
    for (int nn = 0; nn < 2; nn++)
        #pragma unroll
        for (int b = 0; b < 2; b++) {
            const int co = nbase + nn * 8 + q2 + b;
            al[nn * 2 + b] = g_alpha[co];
            bi[nn * 2 + b] = bias[co];
            coff[nn * 2 + b] = (size_t)co * NHW;
        }

    // A/B address constants (SW128 XOR hoisted: row low-3-bits -> v masks)
    uint32_t rbase[7];
    #pragma unroll
    for (int i = 0; i < 7; i++)
        rbase[i] = ((uint32_t)(mbase + i * 16 + lm) << 7) + (uint32_t)lh * 16;
    uint32_t vkw[3];
    #pragma unroll
    for (int kw = 0; kw < 3; kw++)
        vkw[kw] = ((uint32_t)((lm + kw) & 7)) << 4;   // mbase,i*16 are 0 mod 8
    const uint32_t blane = ((uint32_t)lm << 7) + (uint32_t)(nbase + lh * 8) * 2u;
    const uint32_t vb = ((uint32_t)(lm & 7)) << 4;

    __syncthreads();

    const int nb = gridDim.x;
    const int r0 = (int)(((long long)ROWS_TOTAL * blockIdx.x) / nb);
    const int r1 = (int)(((long long)ROWS_TOTAL * (blockIdx.x + 1)) / nb);

    int cur_n = -1;
    for (int r = r0; r < r1; ++r) {
        const int n = r / HW;
        const int h = r - n * HW;

        __syncthreads();                       // ring slot reuse guard
        if (n != cur_n) {
            load_slab(sb, x, n, h + 0, tid);
            load_slab(sb, x, n, h + 1, tid);
            load_slab(sb, x, n, h + 2, tid);
            cur_n = n;
        } else {
            load_slab(sb, x, n, h + 2, tid);   // only the new bottom row
        }
        __syncthreads();

        const uint32_t slabA0 = sb + OFF_SLAB + (uint32_t)((h + 0) & 3) * SLAB_STRIDE;
        const uint32_t slabA1 = sb + OFF_SLAB + (uint32_t)((h + 1) & 3) * SLAB_STRIDE;
        const uint32_t slabA2 = sb + OFF_SLAB + (uint32_t)((h + 2) & 3) * SLAB_STRIDE;

        float acc[56];
        #pragma unroll
        for (int i = 0; i < 56; i++) acc[i] = 0.f;

        const uint32_t bB = sb + OFF_B + blane;

        #define GEMM_BLOCK(KH, KW, SLAB) do {                                   \
            const uint32_t bg = bB + (uint32_t)((KH) * 3 + (KW)) * 8192u;       \
            const uint32_t ap = (SLAB) + ((uint32_t)(KW) << 7);                 \
            _Pragma("unroll")                                                   \
            for (int s = 0; s < 4; s++) {                                       \
                uint32_t bf[4];                                                 \
                ldsm_x4_t(bf, (bg + (uint32_t)s * 2048u) ^ vb);                 \
                const uint32_t pre = ap + (uint32_t)s * 32u;                    \
                _Pragma("unroll")                                               \
                for (int i = 0; i < 7; i++) {                                   \
                    uint32_t af[4];                                             \
                    ldsm_x4(af, (rbase[i] + pre) ^ vkw[KW]);                    \
                    mma16816(acc + i * 8,     af, bf);                          \
                    mma16816(acc + i * 8 + 4, af, bf + 2);                      \
                }                                                               \
            }                                                                   \
        } while (0)

        GEMM_BLOCK(0, 0, slabA0); GEMM_BLOCK(0, 1, slabA0); GEMM_BLOCK(0, 2, slabA0);
        GEMM_BLOCK(1, 0, slabA1); GEMM_BLOCK(1, 1, slabA1); GEMM_BLOCK(1, 2, slabA1);
        GEMM_BLOCK(2, 0, slabA2); GEMM_BLOCK(2, 1, slabA2); GEMM_BLOCK(2, 2, slabA2);
        #undef GEMM_BLOCK

        // epilogue: acc*alpha + bias -> out[n][co][h][w]
        float* orow = out + (size_t)n * NCHW1 + (size_t)h * HW + (lane >> 2);
        #pragma unroll
        for (int i = 0; i < 7; i++) {
            #pragma unroll
            for (int rh = 0; rh < 2; rh++) {
                float* po = orow + (mbase + i * 16 + rh * 8);
                #pragma unroll
                for (int nn = 0; nn < 2; nn++)
                    #pragma unroll
                    for (int b = 0; b < 2; b++)
                        po[coff[nn * 2 + b]] =
                            acc[i * 8 + nn * 4 + rh * 2 + b] * al[nn * 2 + b]
                            + bi[nn * 2 + b];
            }
        }
    }
}

// ============================================================================
// kernel_launch
// ============================================================================
extern "C" void kernel_launch(void* const* d_in, const int* in_sizes, int n_in,
                              void* d_out, int out_size) {
    const float* x    = (const float*)d_in[0];
    const float* wgt  = (const float*)d_in[1];
    const float* bias = (const float*)d_in[2];
    float* out = (float*)d_out;

    int dev = 0;
    cudaGetDevice(&dev);
    int sms = 0;
    cudaDeviceGetAttribute(&sms, cudaDevAttrMultiProcessorCount, dev);
    if (sms <= 0) sms = 148;

    cudaFuncSetAttribute(ternary_conv_kernel,
                         cudaFuncAttributeMaxDynamicSharedMemorySize, SMEM_BYTES);

    prep_ternarize<<<64, 256>>>(wgt);
    ternary_conv_kernel<<<sms, 256, SMEM_BYTES>>>(x, bias, out);
}

// round 15
// speedup vs baseline: 4.9641x; 1.0995x over previous
#include <cuda_runtime.h>
#include <cuda_fp16.h>
#include <cstdint>

// ============================================================================
// TernaryConv2d as shift-GEMM, row-pair tiles:
//   out[co] = alpha[co]*sum_{kh,kw}( x_shift[pix,ci] @ B(kh,kw)[co,ci]^T ) + bias
// Per CTA-tile = TWO output rows (n,h0),(n,h0+1): M=448 pixels, N=64,
// nine K=64 GEMMs. Padded input rows staged as fp16 [wp][ci] SW128 slabs
// (ring of 4; +2 slabs per pair). Warps: 4 M-slices (row r, half) x 2 N(32).
// mma.sync.m16n8k16 f16 -> f32. B ternary {-1,0,1} exact in fp16.
// ============================================================================

#define HW        224
#define NHW       50176
#define NCHW1     3211264
#define PAIRS_TOTAL 1792         // 16*224/2
#define K_TOTAL   576

#define SLAB_STRIDE 29696        // >= 226*128
#define SLAB_BYTES  28928        // 226 rows * 128B
#define OFF_B       0            // 9 * 8192 = 73728
#define OFF_CONST   73728        // alpha[64], bias[64]
#define OFF_SLAB    74752
#define SMEM_BYTES  (OFF_SLAB + 4 * SLAB_STRIDE)   // 193536

#define SW128(o) ((o) ^ (((o) >> 3) & 0x70))

// Scratch (allocation-free rule: __device__ globals)
__device__ __align__(16) unsigned char g_Bsw[9 * 8192];
__device__ float g_alpha[64];

// ============================================================================
// helpers
// ============================================================================
__device__ __forceinline__ uint32_t smem_to_u32(const void* p) {
    uint32_t a;
    asm("{ .reg .u64 t; cvta.to.shared.u64 t, %1; cvt.u32.u64 %0, t; }"
        : "=r"(a) : "l"(p));
    return a;
}
__device__ __forceinline__ void ldsm_x4(uint32_t* r, uint32_t addr) {
    asm volatile("ldmatrix.sync.aligned.m8n8.x4.shared.b16 {%0,%1,%2,%3}, [%4];"
        : "=r"(r[0]), "=r"(r[1]), "=r"(r[2]), "=r"(r[3]) : "r"(addr));
}
__device__ __forceinline__ void ldsm_x4_t(uint32_t* r, uint32_t addr) {
    asm volatile("ldmatrix.sync.aligned.m8n8.x4.trans.shared.b16 {%0,%1,%2,%3}, [%4];"
        : "=r"(r[0]), "=r"(r[1]), "=r"(r[2]), "=r"(r[3]) : "r"(addr));
}
__device__ __forceinline__ void mma16816(float* c, const uint32_t* a, const uint32_t* b) {
    asm volatile(
        "mma.sync.aligned.m16n8k16.row.col.f32.f16.f16.f32 "
        "{%0,%1,%2,%3}, {%4,%5,%6,%7}, {%8,%9}, {%0,%1,%2,%3};"
        : "+f"(c[0]), "+f"(c[1]), "+f"(c[2]), "+f"(c[3])
        : "r"(a[0]), "r"(a[1]), "r"(a[2]), "r"(a[3]), "r"(b[0]), "r"(b[1]));
}
__device__ __forceinline__ uint32_t pack_h2(float lo, float hi) {
    __half2 h = __floats2half2_rn(lo, hi);
    return *reinterpret_cast<uint32_t*>(&h);
}

// ============================================================================
// Prep: TWN ternarize. g_alpha[co]; g_Bsw per gemm g=kh*3+kw:
// [ci=64 rows][128B of co halves] SW128 tile at offset g*8192.
// ============================================================================
__global__ void prep_ternarize(const float* __restrict__ w) {
    const int co = blockIdx.x;
    const float* wc = w + co * K_TOTAL;
    const int tid = threadIdx.x, lane = tid & 31, warp = tid >> 5;

    __shared__ float r1[8], r2[8], r3[8];
    __shared__ float sh_delta;

    float s = 0.f;
    for (int k = tid; k < K_TOTAL; k += 256) s += fabsf(wc[k]);
    #pragma unroll
    for (int o = 16; o; o >>= 1) s += __shfl_xor_sync(0xffffffffu, s, o);
    if (lane == 0) r1[warp] = s;
    __syncthreads();
    if (tid == 0) {
        float tot = 0.f;
        #pragma unroll
        for (int i = 0; i < 8; i++) tot += r1[i];
        sh_delta = (0.7f / 576.f) * tot;
    }
    __syncthreads();
    const float delta = sh_delta;

    float ms = 0.f, mc = 0.f;
    for (int k = tid; k < K_TOTAL; k += 256) {
        float a = fabsf(wc[k]);
        if (a > delta) { ms += a; mc += 1.f; }
    }
    #pragma unroll
    for (int o = 16; o; o >>= 1) {
        ms += __shfl_xor_sync(0xffffffffu, ms, o);
        mc += __shfl_xor_sync(0xffffffffu, mc, o);
    }
    if (lane == 0) { r2[warp] = ms; r3[warp] = mc; }
    __syncthreads();
    if (tid == 0) {
        float tms = 0.f, tmc = 0.f;
        #pragma unroll
        for (int i = 0; i < 8; i++) { tms += r2[i]; tmc += r3[i]; }
        if (tmc < 0.5f) tmc = 1.f;
        float al = tms / tmc;
        if (al < 1e-4f) al = 1e-4f;
        g_alpha[co] = al;
    }

    for (int k = tid; k < K_TOTAL; k += 256) {
        float wv = wc[k];
        float tv = (wv > delta) ? 1.f : ((wv < -delta) ? -1.f : 0.f);
        unsigned ci = (unsigned)k / 9u;
        unsigned g  = (unsigned)k - ci * 9u;    // kh*3+kw
        unsigned off = g * 8192u + SW128(ci * 128u + (unsigned)co * 2u);
        *reinterpret_cast<__half*>(g_Bsw + off) = __float2half_rn(tv);
    }
}

// ============================================================================
// Slab loader: padded row p (input u=p-1) of image n -> ring slot p&3.
// Layout: [wp=0..225] rows of 128B (64 ci halves), SW128. Pads zeroed.
// ============================================================================
__device__ __forceinline__ void load_slab(uint32_t sb, const float* __restrict__ x,
                                          int n, int p, int tid) {
    const uint32_t slot = sb + OFF_SLAB + (uint32_t)(p & 3) * SLAB_STRIDE;
    const int u = p - 1;
    if ((unsigned)u < (unsigned)HW) {
        const int lane = tid & 31;
        const int cib = (tid >> 5) * 8;
        const float* bp = x + (size_t)(n * 64 + cib) * NHW + (size_t)u * HW;
        #pragma unroll
        for (int cp = 0; cp < 4; cp++) {
            const float* p0 = bp + (size_t)(cp * 2) * NHW;
            const float* p1 = p0 + NHW;
            #pragma unroll
            for (int wb = 0; wb < 7; wb++) {
                const int w = wb * 32 + lane;
                const uint32_t h2 = pack_h2(__ldg(p0 + w), __ldg(p1 + w));
                const uint32_t off =
                    SW128(((uint32_t)(w + 1) << 7) + (uint32_t)(cib + cp * 2) * 2u);
                asm volatile("st.shared.b32 [%0], %1;"
                    :: "r"(slot + off), "r"(h2) : "memory");
            }
        }
        if (lane < 4) {   // zero wp=0 / wp=225 pad columns for this warp's ci
            const uint32_t c2 = (uint32_t)(cib + lane * 2) * 2u;
            asm volatile("st.shared.b32 [%0], %1;"
                :: "r"(slot + SW128(c2)), "r"(0u) : "memory");
            asm volatile("st.shared.b32 [%0], %1;"
                :: "r"(slot + SW128((225u << 7) + c2)), "r"(0u) : "memory");
        }
    } else {
        for (int i = tid; i < SLAB_BYTES / 16; i += 256) {
            asm volatile("st.shared.v4.b32 [%0], {%1,%2,%3,%4};"
                :: "r"(slot + (uint32_t)i * 16), "r"(0u), "r"(0u), "r"(0u), "r"(0u)
                : "memory");
        }
    }
}

// ============================================================================
// Main kernel: persistent CTAs walk contiguous row-pair ranges.
// 8 warps: wm=wid>>1 selects (output row r_sel=wm>>1, half mb=(wm&1)*112);
// wn=wid&1 selects n-slice of 32. Per warp: 7 m16 tiles x 4 n8 = 112 acc.
// ============================================================================
__global__ void __launch_bounds__(256, 1)
ternary_conv_kernel(const float* __restrict__ x,
                    const float* __restrict__ bias,
                    float* __restrict__ out) {
    extern __shared__ __align__(1024) unsigned char smem[];
    const uint32_t sb = smem_to_u32(smem);
    const int tid  = threadIdx.x;
    const int lane = tid & 31;
    const int wid  = tid >> 5;
    const int lm = lane & 15, lh = lane >> 4;
    const int wn = wid & 1;
    const int wm = wid >> 1;
    const int r_sel  = wm >> 1;            // which output row of the pair
    const int mbase  = (wm & 1) * 112;     // pixel base within the row
    const int nbase  = wn * 32;

    // one-time: B image + alpha/bias into SMEM
    {
        const uint4* src = reinterpret_cast<const uint4*>(g_Bsw);
        uint4* dst = reinterpret_cast<uint4*>(smem + OFF_B);
        #pragma unroll
        for (int i = 0; i < 18; i++) dst[tid + i * 256] = src[tid + i * 256];
    }
    if (tid < 64) {
        *reinterpret_cast<float*>(smem + OFF_CONST + tid * 4) = g_alpha[tid];
        *reinterpret_cast<float*>(smem + OFF_CONST + 256 + tid * 4) = bias[tid];
    }

    // A/B address constants (SW128 XOR hoisted)
    uint32_t rbase[7];
    #pragma unroll
    for (int i = 0; i < 7; i++)
        rbase[i] = ((uint32_t)(mbase + i * 16 + lm) << 7) + (uint32_t)lh * 16;
    uint32_t vkw[3];
    #pragma unroll
    for (int kw = 0; kw < 3; kw++)
        vkw[kw] = ((uint32_t)((lm + kw) & 7)) << 4;   // mbase, i*16 are 0 mod 8
    const uint32_t blane = ((uint32_t)lm << 7) + (uint32_t)(nbase + lh * 8) * 2u;
    const uint32_t vb = ((uint32_t)(lm & 7)) << 4;
    const uint32_t bB = sb + OFF_B + blane;

    __syncthreads();

    const int nb = gridDim.x;
    const int q0 = (int)(((long long)PAIRS_TOTAL * blockIdx.x) / nb);
    const int q1 = (int)(((long long)PAIRS_TOTAL * (blockIdx.x + 1)) / nb);

    int cur_n = -1, cur_h = -999;
    for (int q = q0; q < q1; ++q) {
        const int n  = q / 112;            // 112 pairs per image
        const int h0 = (q - n * 112) * 2;

        __syncthreads();                   // ring reuse guard
        if (n == cur_n && h0 == cur_h + 2) {
            load_slab(sb, x, n, h0 + 2, tid);
            load_slab(sb, x, n, h0 + 3, tid);
        } else {
            load_slab(sb, x, n, h0 + 0, tid);
            load_slab(sb, x, n, h0 + 1, tid);
            load_slab(sb, x, n, h0 + 2, tid);
            load_slab(sb, x, n, h0 + 3, tid);
        }
        cur_n = n; cur_h = h0;
        __syncthreads();

        // this warp's three slabs: padded rows (h0 + r_sel + kh), kh=0..2
        uint32_t sA[3];
        #pragma unroll
        for (int kh = 0; kh < 3; kh++)
            sA[kh] = sb + OFF_SLAB
                   + (uint32_t)((h0 + r_sel + kh) & 3) * SLAB_STRIDE;

        float acc[112];
        #pragma unroll
        for (int i = 0; i < 112; i++) acc[i] = 0.f;

        #define GEMM_BLOCK(KH, KW) do {                                         \
            const uint32_t bg = bB + (uint32_t)((KH) * 3 + (KW)) * 8192u;       \
            const uint32_t ap = sA[KH] + ((uint32_t)(KW) << 7);                 \
            _Pragma("unroll")                                                   \
            for (int s = 0; s < 4; s++) {                                       \
                uint32_t bf[8];                                                 \
                ldsm_x4_t(bf,     (bg + (uint32_t)s * 2048u) ^ vb);             \
                ldsm_x4_t(bf + 4, (bg + (uint32_t)s * 2048u + 32u) ^ vb);       \
                const uint32_t pre = ap + (uint32_t)s * 32u;                    \
                _Pragma("unroll")                                               \
                for (int i = 0; i < 7; i++) {                                   \
                    uint32_t af[4];                                             \
                    ldsm_x4(af, (rbase[i] + pre) ^ vkw[KW]);                    \
                    mma16816(acc + i * 16,      af, bf);                        \
                    mma16816(acc + i * 16 + 4,  af, bf + 2);                    \
                    mma16816(acc + i * 16 + 8,  af, bf + 4);                    \
                    mma16816(acc + i * 16 + 12, af, bf + 6);                    \
                }                                                               \
            }                                                                   \
        } while (0)

        GEMM_BLOCK(0, 0); GEMM_BLOCK(0, 1); GEMM_BLOCK(0, 2);
        GEMM_BLOCK(1, 0); GEMM_BLOCK(1, 1); GEMM_BLOCK(1, 2);
        GEMM_BLOCK(2, 0); GEMM_BLOCK(2, 1); GEMM_BLOCK(2, 2);
        #undef GEMM_BLOCK

        // epilogue: acc*alpha + bias -> out[n][co][h0+r_sel][w]
        {
            const int q2 = (lane & 3) * 2;
            float al[8], bi[8];
            uint32_t coff[8];
            #pragma unroll
            for (int nn = 0; nn < 4; nn++)
                #pragma unroll
                for (int b = 0; b < 2; b++) {
                    const int co = nbase + nn * 8 + q2 + b;
                    al[nn * 2 + b] =
                        *reinterpret_cast<const float*>(smem + OFF_CONST + co * 4);
                    bi[nn * 2 + b] =
                        *reinterpret_cast<const float*>(smem + OFF_CONST + 256 + co * 4);
                    coff[nn * 2 + b] = (uint32_t)co * NHW;
                }
            float* orow = out + (size_t)n * NCHW1
                        + (size_t)(h0 + r_sel) * HW + (lane >> 2);
            #pragma unroll
            for (int i = 0; i < 7; i++) {
                #pragma unroll
                for (int rh = 0; rh < 2; rh++) {
                    float* po = orow + (mbase + i * 16 + rh * 8);
                    #pragma unroll
                    for (int nn = 0; nn < 4; nn++)
                        #pragma unroll
                        for (int b = 0; b < 2; b++)
                            po[coff[nn * 2 + b]] =
                                acc[i * 16 + nn * 4 + rh * 2 + b] * al[nn * 2 + b]
                                + bi[nn * 2 + b];
                }
            }
        }
    }
}

// ============================================================================
// kernel_launch
// ============================================================================
extern "C" void kernel_launch(void* const* d_in, const int* in_sizes, int n_in,
                              void* d_out, int out_size) {
    const float* x    = (const float*)d_in[0];
    const float* wgt  = (const float*)d_in[1];
    const float* bias = (const float*)d_in[2];
    float* out = (float*)d_out;

    int dev = 0;
    cudaGetDevice(&dev);
    int sms = 0;
    cudaDeviceGetAttribute(&sms, cudaDevAttrMultiProcessorCount, dev);
    if (sms <= 0) sms = 148;

    cudaFuncSetAttribute(ternary_conv_kernel,
                         cudaFuncAttributeMaxDynamicSharedMemorySize, SMEM_BYTES);

    prep_ternarize<<<64, 256>>>(wgt);
    ternary_conv_kernel<<<sms, 256, SMEM_BYTES>>>(x, bias, out);
}

// round 16
// speedup vs baseline: 5.3198x; 1.0717x over previous
#include <cuda_runtime.h>
#include <cuda_fp16.h>
#include <cstdint>

// ============================================================================
// TernaryConv2d as shift-GEMM, row-pair tiles, software-pipelined slab loads:
//   out[co] = alpha[co]*sum_{kh,kw}( x_shift[pix,ci] @ B(kh,kw)[co,ci]^T ) + bias
// Per CTA-tile = TWO output rows: M=448 pixels, N=64, nine K=64 GEMMs.
// Padded input rows live as fp16 [wp][ci] SW128 slabs in a ring of 4.
// Next pair's 2 slabs are LDG'd into registers during this pair's MMA blocks
// and stored into the ring slots as they are vacated (kh-major block order +
// two mid-compute barriers). mma.sync.m16n8k16 f16 -> f32.
// ============================================================================

#define HW        224
#define NHW       50176
#define NCHW1     3211264
#define PAIRS_TOTAL 1792         // 16*224/2
#define K_TOTAL   576

#define SLAB_STRIDE 29696        // >= 226*128
#define SLAB_BYTES  28928        // 226 rows * 128B
#define OFF_B       0            // 9 * 8192 = 73728
#define OFF_CONST   73728        // alpha[64], bias[64]
#define OFF_SLAB    74752
#define SMEM_BYTES  (OFF_SLAB + 4 * SLAB_STRIDE)   // 193536

#define SW128(o) ((o) ^ (((o) >> 3) & 0x70))

// Scratch (allocation-free rule: __device__ globals)
__device__ __align__(16) unsigned char g_Bsw[9 * 8192];
__device__ float g_alpha[64];

// ============================================================================
// helpers
// ============================================================================
__device__ __forceinline__ uint32_t smem_to_u32(const void* p) {
    uint32_t a;
    asm("{ .reg .u64 t; cvta.to.shared.u64 t, %1; cvt.u32.u64 %0, t; }"
        : "=r"(a) : "l"(p));
    return a;
}
__device__ __forceinline__ void ldsm_x4(uint32_t* r, uint32_t addr) {
    asm volatile("ldmatrix.sync.aligned.m8n8.x4.shared.b16 {%0,%1,%2,%3}, [%4];"
        : "=r"(r[0]), "=r"(r[1]), "=r"(r[2]), "=r"(r[3]) : "r"(addr));
}
__device__ __forceinline__ void ldsm_x4_t(uint32_t* r, uint32_t addr) {
    asm volatile("ldmatrix.sync.aligned.m8n8.x4.trans.shared.b16 {%0,%1,%2,%3}, [%4];"
        : "=r"(r[0]), "=r"(r[1]), "=r"(r[2]), "=r"(r[3]) : "r"(addr));
}
__device__ __forceinline__ void mma16816(float* c, const uint32_t* a, const uint32_t* b) {
    asm volatile(
        "mma.sync.aligned.m16n8k16.row.col.f32.f16.f16.f32 "
        "{%0,%1,%2,%3}, {%4,%5,%6,%7}, {%8,%9}, {%0,%1,%2,%3};"
        : "+f"(c[0]), "+f"(c[1]), "+f"(c[2]), "+f"(c[3])
        : "r"(a[0]), "r"(a[1]), "r"(a[2]), "r"(a[3]), "r"(b[0]), "r"(b[1]));
}
__device__ __forceinline__ uint32_t pack_h2(float lo, float hi) {
    __half2 h = __floats2half2_rn(lo, hi);
    return *reinterpret_cast<uint32_t*>(&h);
}

// ============================================================================
// Prep: TWN ternarize. g_alpha[co]; g_Bsw per gemm g=kh*3+kw:
// [ci=64 rows][128B of co halves] SW128 tile at offset g*8192.
// ============================================================================
__global__ void prep_ternarize(const float* __restrict__ w) {
    const int co = blockIdx.x;
    const float* wc = w + co * K_TOTAL;
    const int tid = threadIdx.x, lane = tid & 31, warp = tid >> 5;

    __shared__ float r1[8], r2[8], r3[8];
    __shared__ float sh_delta;

    float s = 0.f;
    for (int k = tid; k < K_TOTAL; k += 256) s += fabsf(wc[k]);
    #pragma unroll
    for (int o = 16; o; o >>= 1) s += __shfl_xor_sync(0xffffffffu, s, o);
    if (lane == 0) r1[warp] = s;
    __syncthreads();
    if (tid == 0) {
        float tot = 0.f;
        #pragma unroll
        for (int i = 0; i < 8; i++) tot += r1[i];
        sh_delta = (0.7f / 576.f) * tot;
    }
    __syncthreads();
    const float delta = sh_delta;

    float ms = 0.f, mc = 0.f;
    for (int k = tid; k < K_TOTAL; k += 256) {
        float a = fabsf(wc[k]);
        if (a > delta) { ms += a; mc += 1.f; }
    }
    #pragma unroll
    for (int o = 16; o; o >>= 1) {
        ms += __shfl_xor_sync(0xffffffffu, ms, o);
        mc += __shfl_xor_sync(0xffffffffu, mc, o);
    }
    if (lane == 0) { r2[warp] = ms; r3[warp] = mc; }
    __syncthreads();
    if (tid == 0) {
        float tms = 0.f, tmc = 0.f;
        #pragma unroll
        for (int i = 0; i < 8; i++) { tms += r2[i]; tmc += r3[i]; }
        if (tmc < 0.5f) tmc = 1.f;
        float al = tms / tmc;
        if (al < 1e-4f) al = 1e-4f;
        g_alpha[co] = al;
    }

    for (int k = tid; k < K_TOTAL; k += 256) {
        float wv = wc[k];
        float tv = (wv > delta) ? 1.f : ((wv < -delta) ? -1.f : 0.f);
        unsigned ci = (unsigned)k / 9u;
        unsigned g  = (unsigned)k - ci * 9u;    // kh*3+kw
        unsigned off = g * 8192u + SW128(ci * 128u + (unsigned)co * 2u);
        *reinterpret_cast<__half*>(g_Bsw + off) = __float2half_rn(tv);
    }
}

// ============================================================================
// Slab helpers. Slab layout: [wp=0..225] rows of 128B (64 ci halves), SW128.
// Per thread: warp owns ci [wid*8, +8), lanes stride w. v4 stores: the 4 ci
// pairs (cp=0..3) are 16 contiguous bytes under SW128 (cib*2 is 16B aligned).
// ============================================================================
__device__ __forceinline__ void slab_pads(uint32_t slot, int cib, int lane) {
    if (lane < 4) {   // zero wp=0 / wp=225 pad pixels for this warp's ci
        const uint32_t c2 = (uint32_t)(cib + lane * 2) * 2u;
        asm volatile("st.shared.b32 [%0], %1;"
            :: "r"(slot + SW128(c2)), "r"(0u) : "memory");
        asm volatile("st.shared.b32 [%0], %1;"
            :: "r"(slot + SW128((225u << 7) + c2)), "r"(0u) : "memory");
    }
}

// Immediate (blocking) slab load: padded row p (input u=p-1) -> ring slot p&3.
__device__ __forceinline__ void load_slab(uint32_t sb, const float* __restrict__ x,
                                          int n, int p, int tid) {
    const uint32_t slot = sb + OFF_SLAB + (uint32_t)(p & 3) * SLAB_STRIDE;
    const int u = p - 1;
    const int lane = tid & 31;
    const int cib = (tid >> 5) * 8;
    if ((unsigned)u < (unsigned)HW) {
        const float* bp = x + (size_t)(n * 64 + cib) * NHW + (size_t)u * HW;
        #pragma unroll
        for (int wb = 0; wb < 7; wb++) {
            const int w = wb * 32 + lane;
            uint32_t h2v[4];
            #pragma unroll
            for (int cp = 0; cp < 4; cp++) {
                const float* p0 = bp + (size_t)(cp * 2) * NHW;
                h2v[cp] = pack_h2(__ldg(p0 + w), __ldg(p0 + NHW + w));
            }
            const uint32_t off = SW128(((uint32_t)(w + 1) << 7) + (uint32_t)cib * 2u);
            asm volatile("st.shared.v4.b32 [%0], {%1,%2,%3,%4};"
                :: "r"(slot + off), "r"(h2v[0]), "r"(h2v[1]), "r"(h2v[2]), "r"(h2v[3])
                : "memory");
        }
        slab_pads(slot, cib, lane);
    } else {
        for (int i = tid; i < SLAB_BYTES / 16; i += 256) {
            asm volatile("st.shared.v4.b32 [%0], {%1,%2,%3,%4};"
                :: "r"(slot + (uint32_t)i * 16), "r"(0u), "r"(0u), "r"(0u), "r"(0u)
                : "memory");
        }
    }
}

// Prefetch issue: LDG input row u (of image n) into 56 fp32 regs. ok=false -> 0.
__device__ __forceinline__ void pf_issue(float* pf, const float* __restrict__ x,
                                         int n, int u, int cib, int lane, bool ok) {
    const float* bp = x + (size_t)(n * 64 + cib) * NHW
                        + (size_t)(ok ? u : 0) * HW;
    #pragma unroll
    for (int cp = 0; cp < 4; cp++) {
        const float* p0 = bp + (size_t)(cp * 2) * NHW;
        const float* p1 = p0 + NHW;
        #pragma unroll
        for (int wb = 0; wb < 7; wb++) {
            const int w = wb * 32 + lane;
            pf[cp * 14 + wb * 2 + 0] = ok ? __ldg(p0 + w) : 0.f;
            pf[cp * 14 + wb * 2 + 1] = ok ? __ldg(p1 + w) : 0.f;
        }
    }
}

// Pack 56 fp32 -> 28 h2 and store slab into ring slot (plus pad pixels).
__device__ __forceinline__ void pf_store(uint32_t slot, const float* pf,
                                         int cib, int lane) {
    #pragma unroll
    for (int wb = 0; wb < 7; wb++) {
        uint32_t h2v[4];
        #pragma unroll
        for (int cp = 0; cp < 4; cp++)
            h2v[cp] = pack_h2(pf[cp * 14 + wb * 2], pf[cp * 14 + wb * 2 + 1]);
        const int w = wb * 32 + lane;
        const uint32_t off = SW128(((uint32_t)(w + 1) << 7) + (uint32_t)cib * 2u);
        asm volatile("st.shared.v4.b32 [%0], {%1,%2,%3,%4};"
            :: "r"(slot + off), "r"(h2v[0]), "r"(h2v[1]), "r"(h2v[2]), "r"(h2v[3])
            : "memory");
    }
    slab_pads(slot, cib, lane);
}

// ============================================================================
// Main kernel: persistent CTAs walk contiguous row-pair ranges.
// 8 warps: wm=wid>>1 -> (output row r_sel=wm>>1, half (wm&1)*112); wn=wid&1.
// kh-major GEMM order + 2 mid-compute barriers lets the next pair's slabs be
// stored into ring slots as the kh groups vacate them.
// ============================================================================
__global__ void __launch_bounds__(256, 1)
ternary_conv_kernel(const float* __restrict__ x,
                    const float* __restrict__ bias,
                    float* __restrict__ out) {
    extern __shared__ __align__(1024) unsigned char smem[];
    const uint32_t sb = smem_to_u32(smem);
    const int tid  = threadIdx.x;
    const int lane = tid & 31;
    const int wid  = tid >> 5;
    const int lm = lane & 15, lh = lane >> 4;
    const int wn = wid & 1;
    const int wm = wid >> 1;
    const int r_sel  = wm >> 1;
    const int mbase  = (wm & 1) * 112;
    const int nbase  = wn * 32;
    const int cib    = wid * 8;            // slab-load ci base

    // one-time: B image + alpha/bias into SMEM
    {
        const uint4* src = reinterpret_cast<const uint4*>(g_Bsw);
        uint4* dst = reinterpret_cast<uint4*>(smem + OFF_B);
        #pragma unroll
        for (int i = 0; i < 18; i++) dst[tid + i * 256] = src[tid + i * 256];
    }
    if (tid < 64) {
        *reinterpret_cast<float*>(smem + OFF_CONST + tid * 4) = g_alpha[tid];
        *reinterpret_cast<float*>(smem + OFF_CONST + 256 + tid * 4) = bias[tid];
    }

    // A/B address constants (SW128 XOR hoisted)
    uint32_t rbase[7];
    #pragma unroll
    for (int i = 0; i < 7; i++)
        rbase[i] = ((uint32_t)(mbase + i * 16 + lm) << 7) + (uint32_t)lh * 16;
    uint32_t vkw[3];
    #pragma unroll
    for (int kw = 0; kw < 3; kw++)
        vkw[kw] = ((uint32_t)((lm + kw) & 7)) << 4;
    const uint32_t blane = ((uint32_t)lm << 7) + (uint32_t)(nbase + lh * 8) * 2u;
    const uint32_t vb = ((uint32_t)(lm & 7)) << 4;
    const uint32_t bB = sb + OFF_B + blane;

    // epilogue constants (loop-invariant)
    const int q2 = (lane & 3) * 2;
    float al[8], bi[8];
    uint32_t coff[8];
    __syncthreads();
    #pragma unroll
    for (int nn = 0; nn < 4; nn++)
        #pragma unroll
        for (int b = 0; b < 2; b++) {
            const int co = nbase + nn * 8 + q2 + b;
            al[nn * 2 + b] =
                *reinterpret_cast<const float*>(smem + OFF_CONST + co * 4);
            bi[nn * 2 + b] =
                *reinterpret_cast<const float*>(smem + OFF_CONST + 256 + co * 4);
            coff[nn * 2 + b] = (uint32_t)co * NHW;
        }

    const int nb = gridDim.x;
    const int q0 = (int)(((long long)PAIRS_TOTAL * blockIdx.x) / nb);
    const int q1 = (int)(((long long)PAIRS_TOTAL * (blockIdx.x + 1)) / nb);

    bool have = false;
    #pragma unroll 1
    for (int q = q0; q < q1; ++q) {
        const int n  = q / 112;
        const int h0 = (q - n * 112) * 2;

        if (!have) {
            __syncthreads();
            load_slab(sb, x, n, h0 + 0, tid);
            load_slab(sb, x, n, h0 + 1, tid);
            load_slab(sb, x, n, h0 + 2, tid);
            load_slab(sb, x, n, h0 + 3, tid);
            __syncthreads();
        }
        const bool same = (q + 1 < q1) && (((q + 1) % 112) != 0);

        uint32_t sA[3];
        #pragma unroll
        for (int kh = 0; kh < 3; kh++)
            sA[kh] = sb + OFF_SLAB
                   + (uint32_t)((h0 + r_sel + kh) & 3) * SLAB_STRIDE;

        float acc[112];
        #pragma unroll
        for (int i = 0; i < 112; i++) acc[i] = 0.f;

        #define GEMM_BLOCK(KH, KW) do {                                         \
            const uint32_t bg = bB + (uint32_t)((KH) * 3 + (KW)) * 8192u;       \
            const uint32_t ap = sA[KH] + ((uint32_t)(KW) << 7);                 \
            _Pragma("unroll")                                                   \
            for (int s = 0; s < 4; s++) {                                       \
                uint32_t bf[8];                                                 \
                ldsm_x4_t(bf,     (bg + (uint32_t)s * 2048u) ^ vb);             \
                ldsm_x4_t(bf + 4, (bg + (uint32_t)s * 2048u + 32u) ^ vb);       \
                const uint32_t pre = ap + (uint32_t)s * 32u;                    \
                _Pragma("unroll")                                               \
                for (int i = 0; i < 7; i++) {                                   \
                    uint32_t af[4];                                             \
                    ldsm_x4(af, (rbase[i] + pre) ^ vkw[KW]);                    \
                    mma16816(acc + i * 16,      af, bf);                        \
                    mma16816(acc + i * 16 + 4,  af, bf + 2);                    \
                    mma16816(acc + i * 16 + 8,  af, bf + 4);                    \
                    mma16816(acc + i * 16 + 12, af, bf + 6);                    \
                }                                                               \
            }                                                                   \
        } while (0)

        float pf[56];

        // prefetch slab p=h0+4 (input row u=h0+3) during kh=0 group
        if (same) pf_issue(pf, x, n, h0 + 3, cib, lane, (h0 + 3) < HW);

        GEMM_BLOCK(0, 0); GEMM_BLOCK(0, 1); GEMM_BLOCK(0, 2);
        __syncthreads();               // slab h0 (slot h0&3) now vacated
        if (same) {
            pf_store(sb + OFF_SLAB + (uint32_t)((h0 + 4) & 3) * SLAB_STRIDE,
                     pf, cib, lane);
            // prefetch slab p=h0+5 (input row u=h0+4) during kh=1 group
            pf_issue(pf, x, n, h0 + 4, cib, lane, (h0 + 4) < HW);
        }

        GEMM_BLOCK(1, 0); GEMM_BLOCK(1, 1); GEMM_BLOCK(1, 2);
        __syncthreads();               // slab h0+1 (slot (h0+1)&3) now vacated
        if (same) {
            pf_store(sb + OFF_SLAB + (uint32_t)((h0 + 5) & 3) * SLAB_STRIDE,
                     pf, cib, lane);
        }

        GEMM_BLOCK(2, 0); GEMM_BLOCK(2, 1); GEMM_BLOCK(2, 2);
        #undef GEMM_BLOCK

        // epilogue: acc*alpha + bias -> out[n][co][h0+r_sel][w]
        {
            float* orow = out + (size_t)n * NCHW1
                        + (size_t)(h0 + r_sel) * HW + (lane >> 2);
            #pragma unroll
            for (int i = 0; i < 7; i++) {
                #pragma unroll
                for (int rh = 0; rh < 2; rh++) {
                    float* po = orow + (mbase + i * 16 + rh * 8);
                    #pragma unroll
                    for (int nn = 0; nn < 4; nn++)
                        #pragma unroll
                        for (int b = 0; b < 2; b++)
                            po[coff[nn * 2 + b]] =
                                acc[i * 16 + nn * 4 + rh * 2 + b] * al[nn * 2 + b]
                                + bi[nn * 2 + b];
                }
            }
        }

        have = same;
    }
}

// ============================================================================
// kernel_launch
// ============================================================================
extern "C" void kernel_launch(void* const* d_in, const int* in_sizes, int n_in,
                              void* d_out, int out_size) {
    const float* x    = (const float*)d_in[0];
    const float* wgt  = (const float*)d_in[1];
    const float* bias = (const float*)d_in[2];
    float* out = (float*)d_out;

    int dev = 0;
    cudaGetDevice(&dev);
    int sms = 0;
    cudaDeviceGetAttribute(&sms, cudaDevAttrMultiProcessorCount, dev);
    if (sms <= 0) sms = 148;

    cudaFuncSetAttribute(ternary_conv_kernel,
                         cudaFuncAttributeMaxDynamicSharedMemorySize, SMEM_BYTES);

    prep_ternarize<<<64, 256>>>(wgt);
    ternary_conv_kernel<<<sms, 256, SMEM_BYTES>>>(x, bias, out);
}